// round 6
// baseline (speedup 1.0000x reference)
#include <cuda_runtime.h>
#include <cstdint>
#include <cstddef>

#define SLEN 2048
#define HD 64
#define NBH 64
#define TQ 128
#define TKV 64
#define PADQ 72   // qs/ks row stride (floats), permuted layout, conflict-free LDS.64
#define PADV 72   // vs row stride
#define PADP 36   // per-warp e-staging row stride (flash)
#define PADE 72   // es row stride (attn store staging)
#define NTHREADS 256

// per-row log(sum exp(s)) scratch
__device__ float g_lnl[(size_t)NBH * SLEN];

// ---------------- kernel 1 smem layout (floats) ----------------
// qs[128*72]=9216 | ks[64*72]=4608 | vs[64*72]=4608 | ps[8*32*36]=9216 | lpart[256] | ls[128]
// obuf[128*68]=8704 aliases ks+vs after main loop
#define K1_QS 0
#define K1_KS 9216
#define K1_VS 13824
#define K1_PS 18432
#define K1_LP 27648
#define K1_LS 27904
#define K1_OB 9216
#define K1_SMEM_FLOATS 28032
#define K1_SMEM_BYTES (K1_SMEM_FLOATS * 4)   // 112128

// ---------------- kernel 2 smem layout ----------------
// qs[128*68]=8704 (unpermuted, scalar hoist) | ks[64*72]=4608 (perm) | es[128*72]=9216
#define K2_QS 0
#define K2_KS 8704
#define K2_ES 13312
#define K2_SMEM_FLOATS 22528
#define K2_SMEM_BYTES (K2_SMEM_FLOATS * 4)   // 90112

__device__ __forceinline__ uint32_t f2tf32(float f) {
    uint32_t u;
    asm("cvt.rna.tf32.f32 %0, %1;\n" : "=r"(u) : "f"(f));
    return u;
}

__device__ __forceinline__ void mma_tf32(float c[4],
    uint32_t a0, uint32_t a1, uint32_t a2, uint32_t a3,
    uint32_t b0, uint32_t b1)
{
    asm volatile(
        "mma.sync.aligned.m16n8k8.row.col.f32.tf32.tf32.f32 "
        "{%0,%1,%2,%3}, {%4,%5,%6,%7}, {%8,%9}, {%0,%1,%2,%3};\n"
        : "+f"(c[0]), "+f"(c[1]), "+f"(c[2]), "+f"(c[3])
        : "r"(a0), "r"(a1), "r"(a2), "r"(a3), "r"(b0), "r"(b1));
}

// permuted physical column for logical col within row:
// group of 8: [0,4,1,5,2,6,3,7] -> logical qd and qd+4 land adjacent (2qd, 2qd+1)
// For a float4 store at logical cols c4*4+j (j=0..3):
//   physical = (c4>>1)*8 + 2*j + (c4&1)
__device__ __forceinline__ int permcol(int c4, int j) {
    return ((c4 >> 1) << 3) + (j << 1) + (c4 & 1);
}

// ============ kernel 1: flash fwd (no attn write), O and log-l ============
__global__ __launch_bounds__(NTHREADS, 2)
void sdpa_flash(const float* __restrict__ q, const float* __restrict__ k,
                const float* __restrict__ v, float* __restrict__ out)
{
    extern __shared__ float smem[];
    float* qs = smem + K1_QS;
    float* ks = smem + K1_KS;
    float* vs = smem + K1_VS;
    float* ps = smem + K1_PS;
    float* lpart = smem + K1_LP;
    float* ls = smem + K1_LS;
    float* obuf = smem + K1_OB;

    const int qt = blockIdx.x, bh = blockIdx.y;
    const int q0 = qt * TQ;
    const int tid = threadIdx.x;
    const int lane = tid & 31, warp = tid >> 5;
    const int g = lane >> 2, qd = lane & 3;
    const int wr = warp >> 1, wc = warp & 1;
    const int rbase = wr * 32;

    const float* qg = q + (size_t)bh * SLEN * HD;
    const float* kg = k + (size_t)bh * SLEN * HD;
    const float* vg = v + (size_t)bh * SLEN * HD;
    float* og = out + (size_t)bh * SLEN * HD;

    // Q tile (scaled by 1/8), tf32, PERMUTED columns, stride 72
    {
        const float4* qg4 = (const float4*)(qg + (size_t)q0 * HD);
        #pragma unroll
        for (int i = 0; i < 8; i++) {
            int vv = tid + i * NTHREADS;       // 2048 float4 = 128x64
            int r = vv >> 4, c4 = vv & 15;
            float4 t = qg4[vv];
            uint32_t* row = (uint32_t*)&qs[r * PADQ];
            row[permcol(c4, 0)] = f2tf32(t.x * 0.125f);
            row[permcol(c4, 1)] = f2tf32(t.y * 0.125f);
            row[permcol(c4, 2)] = f2tf32(t.z * 0.125f);
            row[permcol(c4, 3)] = f2tf32(t.w * 0.125f);
        }
    }

    float lsum[4] = {0.f, 0.f, 0.f, 0.f};
    float o[2][8][4];
    #pragma unroll
    for (int mi = 0; mi < 2; mi++)
        #pragma unroll
        for (int n = 0; n < 8; n++)
            { o[mi][n][0]=0.f; o[mi][n][1]=0.f; o[mi][n][2]=0.f; o[mi][n][3]=0.f; }

    const uint32_t wb = warp * (32 * PADP);
    uint32_t* psw = (uint32_t*)ps;

    for (int kt = 0; kt < SLEN / TKV; kt++) {
        __syncthreads();   // prior iteration reads of ks/vs complete
        // K (permuted) and V (plain) tiles 64x64 -> smem tf32
        const float4* kg4 = (const float4*)(kg + (size_t)kt * TKV * HD);
        const float4* vg4 = (const float4*)(vg + (size_t)kt * TKV * HD);
        #pragma unroll
        for (int i = 0; i < 4; i++) {
            int vv = tid + i * NTHREADS;       // 1024 float4 = 64x64
            int r = vv >> 4, c4 = vv & 15;
            float4 t = kg4[vv];
            uint32_t* row = (uint32_t*)&ks[r * PADQ];
            row[permcol(c4, 0)] = f2tf32(t.x);
            row[permcol(c4, 1)] = f2tf32(t.y);
            row[permcol(c4, 2)] = f2tf32(t.z);
            row[permcol(c4, 3)] = f2tf32(t.w);
            float4 u = vg4[vv];
            uint32_t* dv = (uint32_t*)&vs[r * PADV + c4 * 4];
            dv[0] = f2tf32(u.x); dv[1] = f2tf32(u.y);
            dv[2] = f2tf32(u.z); dv[3] = f2tf32(u.w);
        }
        __syncthreads();

        // QK: warp tile 32 rows x 32 cols, LDS.64 fragment loads
        float c[2][4][4];
        #pragma unroll
        for (int mi = 0; mi < 2; mi++)
            #pragma unroll
            for (int n = 0; n < 4; n++)
                { c[mi][n][0]=0.f; c[mi][n][1]=0.f; c[mi][n][2]=0.f; c[mi][n][3]=0.f; }

        #pragma unroll
        for (int kk = 0; kk < 8; kk++) {
            int kc = kk * 8 + 2 * qd;   // physical: (logical qd, qd+4) adjacent
            uint32_t a[2][4];
            #pragma unroll
            for (int mi = 0; mi < 2; mi++) {
                int r = rbase + mi * 16 + g;
                uint2 lo = *(const uint2*)&qs[r * PADQ + kc];        // (a0, a2)
                uint2 hi = *(const uint2*)&qs[(r + 8) * PADQ + kc];  // (a1, a3)
                a[mi][0] = lo.x; a[mi][1] = hi.x; a[mi][2] = lo.y; a[mi][3] = hi.y;
            }
            #pragma unroll
            for (int n = 0; n < 4; n++) {
                int cc = wc * 32 + n * 8 + g;
                uint2 bb = *(const uint2*)&ks[cc * PADQ + kc];       // (b0, b1)
                mma_tf32(c[0][n], a[0][0], a[0][1], a[0][2], a[0][3], bb.x, bb.y);
                mma_tf32(c[1][n], a[1][0], a[1][1], a[1][2], a[1][3], bb.x, bb.y);
            }
        }

        // e = exp(s); accumulate l; stage e (tf32) in per-warp block (STS.64)
        #pragma unroll
        for (int mi = 0; mi < 2; mi++) {
            int lr = mi * 16 + g;
            #pragma unroll
            for (int n = 0; n < 4; n++) {
                float e0 = __expf(c[mi][n][0]);
                float e1 = __expf(c[mi][n][1]);
                float e2 = __expf(c[mi][n][2]);
                float e3 = __expf(c[mi][n][3]);
                lsum[2 * mi]     += e0 + e1;
                lsum[2 * mi + 1] += e2 + e3;
                uint2 p0; p0.x = f2tf32(e0); p0.y = f2tf32(e1);
                uint2 p1; p1.x = f2tf32(e2); p1.y = f2tf32(e3);
                *(uint2*)&psw[wb + lr * PADP + n * 8 + 2 * qd] = p0;
                *(uint2*)&psw[wb + (lr + 8) * PADP + n * 8 + 2 * qd] = p1;
            }
        }
        __syncwarp();

        // PV: o += e(32xk32) * V(k32 x 64)
        const uint32_t* vsu = (const uint32_t*)vs;
        #pragma unroll
        for (int kk2 = 0; kk2 < 4; kk2++) {
            uint32_t a[2][4];
            #pragma unroll
            for (int mi = 0; mi < 2; mi++) {
                int lr = mi * 16 + g;
                a[mi][0] = psw[wb + lr * PADP + kk2 * 8 + qd];
                a[mi][1] = psw[wb + (lr + 8) * PADP + kk2 * 8 + qd];
                a[mi][2] = psw[wb + lr * PADP + kk2 * 8 + qd + 4];
                a[mi][3] = psw[wb + (lr + 8) * PADP + kk2 * 8 + qd + 4];
            }
            int vr = wc * 32 + kk2 * 8 + qd;
            #pragma unroll
            for (int n = 0; n < 8; n++) {
                uint32_t b0 = vsu[vr * PADV + n * 8 + g];
                uint32_t b1 = vsu[(vr + 4) * PADV + n * 8 + g];
                mma_tf32(o[0][n], a[0][0], a[0][1], a[0][2], a[0][3], b0, b1);
                mma_tf32(o[1][n], a[1][0], a[1][1], a[1][2], a[1][3], b0, b1);
            }
        }
    }

    // reduce l across quad, then across wc halves
    #pragma unroll
    for (int j = 0; j < 4; j++) {
        lsum[j] += __shfl_xor_sync(0xffffffffu, lsum[j], 1);
        lsum[j] += __shfl_xor_sync(0xffffffffu, lsum[j], 2);
    }
    if (qd == 0) {
        #pragma unroll
        for (int j = 0; j < 4; j++) {
            int row = rbase + (j >> 1) * 16 + (j & 1) * 8 + g;
            lpart[wc * 128 + row] = lsum[j];
        }
    }
    __syncthreads();
    if (tid < TQ) {
        float L = lpart[tid] + lpart[128 + tid];
        ls[tid] = __frcp_rn(L);
        g_lnl[(size_t)bh * SLEN + q0 + tid] = __logf(L);
    }
    __syncthreads();

    // combine O across wc halves, scale, store (obuf stride 68)
    if (wc == 1) {
        #pragma unroll
        for (int mi = 0; mi < 2; mi++) {
            int row = rbase + mi * 16 + g;
            #pragma unroll
            for (int n = 0; n < 8; n++) {
                obuf[row * 68 + n * 8 + 2 * qd]     = o[mi][n][0];
                obuf[row * 68 + n * 8 + 2 * qd + 1] = o[mi][n][1];
                obuf[(row + 8) * 68 + n * 8 + 2 * qd]     = o[mi][n][2];
                obuf[(row + 8) * 68 + n * 8 + 2 * qd + 1] = o[mi][n][3];
            }
        }
    }
    __syncthreads();
    if (wc == 0) {
        #pragma unroll
        for (int mi = 0; mi < 2; mi++) {
            int row = rbase + mi * 16 + g;
            float inv0 = ls[row], inv1 = ls[row + 8];
            float* orow0 = og + (size_t)(q0 + row) * HD;
            float* orow1 = orow0 + (size_t)8 * HD;
            #pragma unroll
            for (int n = 0; n < 8; n++) {
                int col = n * 8 + 2 * qd;
                float x0 = (o[mi][n][0] + obuf[row * 68 + col]) * inv0;
                float x1 = (o[mi][n][1] + obuf[row * 68 + col + 1]) * inv0;
                float x2 = (o[mi][n][2] + obuf[(row + 8) * 68 + col]) * inv1;
                float x3 = (o[mi][n][3] + obuf[(row + 8) * 68 + col + 1]) * inv1;
                *(float2*)(orow0 + col) = make_float2(x0, x1);
                *(float2*)(orow1 + col) = make_float2(x2, x3);
            }
        }
    }
}

// ============ kernel 2: recompute S, write attn = exp(s - lnl) ============
// Q a-frags hoisted in registers; K permuted (LDS.64 b-frags);
// stores transposed through smem for fully coalesced STG.128.
__global__ __launch_bounds__(NTHREADS, 2)
void sdpa_attn(const float* __restrict__ q, const float* __restrict__ k,
               float* __restrict__ attn)
{
    extern __shared__ float smem[];
    float* qs = smem + K2_QS;
    float* ks = smem + K2_KS;
    float* es = smem + K2_ES;

    const int qt = blockIdx.x, bh = blockIdx.y;
    const int q0 = qt * TQ;
    const int tid = threadIdx.x;
    const int lane = tid & 31, warp = tid >> 5;
    const int g = lane >> 2, qd = lane & 3;
    const int wr = warp >> 1, wc = warp & 1;
    const int rbase = wr * 32;

    const float* qg = q + (size_t)bh * SLEN * HD;
    const float* kg = k + (size_t)bh * SLEN * HD;
    float* ag = attn + (size_t)bh * SLEN * SLEN;

    {
        const float4* qg4 = (const float4*)(qg + (size_t)q0 * HD);
        #pragma unroll
        for (int i = 0; i < 8; i++) {
            int vv = tid + i * NTHREADS;
            int r = vv >> 4, c4 = vv & 15;
            float4 t = qg4[vv];
            uint32_t* dst = (uint32_t*)&qs[r * 68 + c4 * 4];
            dst[0] = f2tf32(t.x * 0.125f);
            dst[1] = f2tf32(t.y * 0.125f);
            dst[2] = f2tf32(t.z * 0.125f);
            dst[3] = f2tf32(t.w * 0.125f);
        }
    }
    __syncthreads();

    // hoist Q a-fragments into registers (qs never re-read afterwards)
    uint32_t qa[2][8][4];
    {
        const uint32_t* qsu = (const uint32_t*)qs;
        #pragma unroll
        for (int kk = 0; kk < 8; kk++)
            #pragma unroll
            for (int mi = 0; mi < 2; mi++) {
                int r = rbase + mi * 16 + g;
                qa[mi][kk][0] = qsu[r * 68 + kk * 8 + qd];
                qa[mi][kk][1] = qsu[(r + 8) * 68 + kk * 8 + qd];
                qa[mi][kk][2] = qsu[r * 68 + kk * 8 + qd + 4];
                qa[mi][kk][3] = qsu[(r + 8) * 68 + kk * 8 + qd + 4];
            }
    }

    // per-thread row lnl (4 rows)
    float lnl[4];
    #pragma unroll
    for (int j = 0; j < 4; j++) {
        int row = rbase + (j >> 1) * 16 + (j & 1) * 8 + g;
        lnl[j] = g_lnl[(size_t)bh * SLEN + q0 + row];
    }

    for (int kt = 0; kt < SLEN / TKV; kt++) {
        // prefetch K tile before the barrier
        const float4* kg4 = (const float4*)(kg + (size_t)kt * TKV * HD);
        float4 kreg[4];
        #pragma unroll
        for (int i = 0; i < 4; i++)
            kreg[i] = kg4[tid + i * NTHREADS];
        __syncthreads();   // closes prev LDS(es)/mma(ks) reads
        #pragma unroll
        for (int i = 0; i < 4; i++) {
            int vv = tid + i * NTHREADS;
            int r = vv >> 4, c4 = vv & 15;
            uint32_t* row = (uint32_t*)&ks[r * PADQ];
            row[permcol(c4, 0)] = f2tf32(kreg[i].x);
            row[permcol(c4, 1)] = f2tf32(kreg[i].y);
            row[permcol(c4, 2)] = f2tf32(kreg[i].z);
            row[permcol(c4, 3)] = f2tf32(kreg[i].w);
        }
        __syncthreads();

        float c[2][4][4];
        #pragma unroll
        for (int mi = 0; mi < 2; mi++)
            #pragma unroll
            for (int n = 0; n < 4; n++)
                { c[mi][n][0]=0.f; c[mi][n][1]=0.f; c[mi][n][2]=0.f; c[mi][n][3]=0.f; }

        #pragma unroll
        for (int kk = 0; kk < 8; kk++) {
            int kc = kk * 8 + 2 * qd;
            #pragma unroll
            for (int n = 0; n < 4; n++) {
                int cc = wc * 32 + n * 8 + g;
                uint2 bb = *(const uint2*)&ks[cc * PADQ + kc];   // (b0, b1)
                mma_tf32(c[0][n], qa[0][kk][0], qa[0][kk][1], qa[0][kk][2], qa[0][kk][3], bb.x, bb.y);
                mma_tf32(c[1][n], qa[1][kk][0], qa[1][kk][1], qa[1][kk][2], qa[1][kk][3], bb.x, bb.y);
            }
        }

        // p = exp(s - lnl) -> stage into es (STS.64, conflict-free)
        #pragma unroll
        for (int mi = 0; mi < 2; mi++) {
            int row = rbase + mi * 16 + g;
            float l0 = lnl[2 * mi], l1 = lnl[2 * mi + 1];
            #pragma unroll
            for (int n = 0; n < 4; n++) {
                int col = wc * 32 + n * 8 + 2 * qd;
                float p0 = __expf(c[mi][n][0] - l0);
                float p1 = __expf(c[mi][n][1] - l0);
                float p2 = __expf(c[mi][n][2] - l1);
                float p3 = __expf(c[mi][n][3] - l1);
                *(float2*)&es[row * PADE + col] = make_float2(p0, p1);
                *(float2*)&es[(row + 8) * PADE + col] = make_float2(p2, p3);
            }
        }
        __syncthreads();

        // coalesced write-out: 128x64 tile, float4 rows
        #pragma unroll
        for (int i = 0; i < 8; i++) {
            int vv = tid + i * NTHREADS;    // 2048 float4 = 128x64
            int r = vv >> 4, c4 = vv & 15;
            float4 t = *(const float4*)&es[r * PADE + c4 * 4];
            *(float4*)(ag + (size_t)(q0 + r) * SLEN + kt * TKV + c4 * 4) = t;
        }
    }
}

extern "C" void kernel_launch(void* const* d_in, const int* in_sizes, int n_in,
                              void* d_out, int out_size)
{
    const float* q = (const float*)d_in[0];
    const float* k = (const float*)d_in[1];
    const float* v = (const float*)d_in[2];
    float* out  = (float*)d_out;
    float* attn = out + (size_t)NBH * SLEN * HD;

    cudaFuncSetAttribute(sdpa_flash, cudaFuncAttributeMaxDynamicSharedMemorySize, K1_SMEM_BYTES);
    cudaFuncSetAttribute(sdpa_attn,  cudaFuncAttributeMaxDynamicSharedMemorySize, K2_SMEM_BYTES);

    dim3 grid(SLEN / TQ, NBH);
    sdpa_flash<<<grid, NTHREADS, K1_SMEM_BYTES>>>(q, k, v, out);
    sdpa_attn<<<grid, NTHREADS, K2_SMEM_BYTES>>>(q, k, attn);
}